// round 3
// baseline (speedup 1.0000x reference)
#include <cuda_runtime.h>

#define FULL 0xffffffffu

static constexpr int B   = 256;
static constexpr int D   = 128;
static constexpr int K   = 8192;
static constexpr int KP1 = K + 1;
static constexpr int ENT = B * KP1;                 // 2,097,408
static constexpr int NROWS = 500000;
static constexpr int BUCKET_ROWS = 64;
static constexpr int NBUCK = (NROWS + BUCKET_ROWS - 1) / BUCKET_ROWS;  // 7813
static constexpr long long BANK  = (long long)NROWS * D;   // 64,000,000 floats
static constexpr long long BANK4 = BANK / 4;               // 16,000,000 float4

__device__ int    g_cnt[NBUCK];
__device__ int    g_off[NBUCK + 1];
__device__ int    g_cur[NBUCK];
__device__ uint2  g_ent[ENT];         // {row, (b<<1)|is_positive}
__device__ float  g_sc0[ENT];         // view0 = exp(<w_v2,f_s>/T), sign-flagged
__device__ float  g_sc1[ENT];         // view1 = exp(<w_v1,f_t>/T), sign-flagged
__device__ double g_sum[2];
__device__ double g_loss;
__device__ int    g_winner[B];

__device__ __forceinline__ float kINV_T() { return (float)(1.0 / 0.07); }
__device__ __forceinline__ float kMPN()   { return (float)(8192.0 / 500000.0); }
__device__ __forceinline__ float kDENOM() { return (float)(8192.0 / 500000.0 + 1e-7); }

// --- init: zero counters/sums, winners, head/tail copy scalars
__global__ void k_zero(const int* __restrict__ idx,
                       const float* __restrict__ mv1, const float* __restrict__ mv2,
                       float* __restrict__ out) {
    int t = blockIdx.x * 256 + threadIdx.x;   // 8192 threads
    if (t < NBUCK) g_cnt[t] = 0;
    if (t < 2) g_sum[t] = 0.0;
    if (t == 2) g_loss = 0.0;
    if (t == 3) {
        out[1] = mv1[0]; out[2] = mv1[1]; out[3] = mv1[2];
        out[BANK] = mv1[BANK - 1];
        out[1 + BANK] = mv2[0]; out[2 + BANK] = mv2[1]; out[3 + BANK] = mv2[2];
        out[2 * BANK] = mv2[BANK - 1];
    }
    if (t < B) {
        int my = idx[t];
        int win = 1;
        for (int b2 = t + 1; b2 < B; b2++)
            if (idx[b2] == my) win = 0;
        g_winner[t] = win;
    }
}

// --- histogram of references by row bucket
__global__ void k_hist(const int* __restrict__ idx, const int* __restrict__ cidx) {
    int t = blockIdx.x * 256 + threadIdx.x;   // 262144 threads
    for (int e = t; e < ENT; e += 262144) {
        int b = e / KP1;
        int kpos = e - b * KP1;
        int row = kpos ? cidx[b * K + kpos - 1] : idx[b];
        atomicAdd(&g_cnt[row >> 6], 1);
    }
}

// --- exclusive scan over 7813 bucket counts (single block)
__global__ void k_scan() {
    __shared__ int sh[1024];
    int t = threadIdx.x;
    int base = t * 8;
    int loc[8];
    int s = 0;
    #pragma unroll
    for (int i = 0; i < 8; i++) {
        int v = (base + i < NBUCK) ? g_cnt[base + i] : 0;
        loc[i] = s;
        s += v;
    }
    sh[t] = s;
    __syncthreads();
    for (int off = 1; off < 1024; off <<= 1) {
        int v = (t >= off) ? sh[t - off] : 0;
        __syncthreads();
        sh[t] += v;
        __syncthreads();
    }
    int pre = (t > 0) ? sh[t - 1] : 0;
    #pragma unroll
    for (int i = 0; i < 8; i++) {
        if (base + i < NBUCK) {
            int o = pre + loc[i];
            g_off[base + i] = o;
            g_cur[base + i] = o;
        }
    }
    if (t == 1023) g_off[NBUCK] = sh[1023];
}

// --- scatter references into row-bucket order
__global__ void k_scatter(const int* __restrict__ idx, const int* __restrict__ cidx) {
    int t = blockIdx.x * 256 + threadIdx.x;
    for (int e = t; e < ENT; e += 262144) {
        int b = e / KP1;
        int kpos = e - b * KP1;
        int row = kpos ? cidx[b * K + kpos - 1] : idx[b];
        int pos = atomicAdd(&g_cur[row >> 6], 1);
        g_ent[pos] = make_uint2((unsigned)row, ((unsigned)b << 1) | (kpos == 0 ? 1u : 0u));
    }
}

// --- main fused kernel: per bucket — stream rows to SMEM + out, then score
__global__ void __launch_bounds__(256) k_main(
        const float* __restrict__ f_s, const float* __restrict__ f_t,
        const float* __restrict__ mv1, const float* __restrict__ mv2,
        float* __restrict__ out) {
    extern __shared__ float4 sm4[];    // [0..2047] bank1 rows, [2048..4095] bank2 rows
    __shared__ double shs[16];

    int beta = blockIdx.x;
    int s_row = beta * BUCKET_ROWS;
    int nrows = min(BUCKET_ROWS, NROWS - s_row);
    int nf4 = nrows * 32;
    long long s4 = (long long)s_row * 32;

    // ---- phase 1: stage bucket rows into smem; fused shifted-float4 copy to out
    float4* out4 = (float4*)out;
    #pragma unroll 2
    for (int v = 0; v < 2; v++) {
        const float4* bank4 = (const float4*)(v ? mv2 : mv1);
        const float*  bankf = v ? mv2 : mv1;
        for (int j0 = threadIdx.x; j0 < nf4; j0 += 256) {
            long long m = s4 + j0;
            float4 c = bank4[m];
            sm4[v * 2048 + j0] = c;
            if (m != 0) {
                float prev = bankf[4 * m - 1];
                __stcs(&out4[(long long)v * BANK4 + m],
                       make_float4(prev, c.x, c.y, c.z));
            }
        }
    }
    __syncthreads();

    // ---- phase 2: score all entries of this bucket from smem
    int base = g_off[beta];
    int end  = g_off[beta + 1];
    int lane = threadIdx.x & 31;
    int wrp  = threadIdx.x >> 5;
    const float4* fs4 = (const float4*)f_s;
    const float4* ft4 = (const float4*)f_t;

    double acc0 = 0.0, acc1 = 0.0;

    for (int e0 = base + wrp * 8; e0 < end; e0 += 64) {
        int cnt = min(8, end - e0);
        uint2 ent = make_uint2((unsigned)s_row, 0u);
        if (lane < cnt) ent = g_ent[e0 + lane];

        float d0[8], d1[8];
        #pragma unroll
        for (int j = 0; j < 8; j++) {
            int row  = (int)__shfl_sync(FULL, ent.x, j) - s_row;
            int meta = (int)__shfl_sync(FULL, ent.y, j);
            int b = meta >> 1;
            float4 rA = sm4[row * 32 + lane];          // mv1 row
            float4 rB = sm4[2048 + row * 32 + lane];   // mv2 row
            float4 fvs = fs4[b * 32 + lane];
            float4 fvt = ft4[b * 32 + lane];
            d0[j] = rB.x * fvs.x + rB.y * fvs.y + rB.z * fvs.z + rB.w * fvs.w;
            d1[j] = rA.x * fvt.x + rA.y * fvt.y + rA.z * fvt.z + rA.w * fvt.w;
        }
        #pragma unroll
        for (int off = 16; off > 0; off >>= 1) {
            #pragma unroll
            for (int j = 0; j < 8; j++) {
                d0[j] += __shfl_xor_sync(FULL, d0[j], off);
                d1[j] += __shfl_xor_sync(FULL, d1[j], off);
            }
        }
        #pragma unroll
        for (int j = 0; j < 8; j++) {
            int meta = (int)__shfl_sync(FULL, ent.y, j);
            if (lane == 0 && j < cnt) {
                float w0 = expf(d0[j] * kINV_T());
                float w1 = expf(d1[j] * kINV_T());
                bool pos = (meta & 1) != 0;
                g_sc0[e0 + j] = pos ? -w0 : w0;
                g_sc1[e0 + j] = pos ? -w1 : w1;
                acc0 += (double)w0;
                acc1 += (double)w1;
            }
        }
    }

    // block-level reduction of Z partial sums -> 2 atomics per block
    if (lane == 0) { shs[wrp] = acc0; shs[8 + wrp] = acc1; }
    __syncthreads();
    if (threadIdx.x == 0) {
        double s0 = 0.0, s1 = 0.0;
        #pragma unroll
        for (int j = 0; j < 8; j++) { s0 += shs[j]; s1 += shs[8 + j]; }
        atomicAdd(&g_sum[0], s0);
        atomicAdd(&g_sum[1], s1);
    }
}

// --- loss reduction over linear score arrays
__global__ void __launch_bounds__(256) k2_loss() {
    double Z0 = g_sum[0] * (500000.0 / 2097408.0);
    double Z1 = g_sum[1] * (500000.0 / 2097408.0);
    float Zf0 = (float)Z0, Zf1 = (float)Z1;

    const int NT = 512 * 256;
    int tid = blockIdx.x * 256 + threadIdx.x;
    double acc = 0.0;

    #pragma unroll 4
    for (int i = tid; i < 2 * ENT; i += NT) {
        int v1 = (i >= ENT);
        float s = v1 ? g_sc1[i - ENT] : g_sc0[i];
        float Zf = v1 ? Zf1 : Zf0;
        float y = fabsf(s) / Zf;
        float t = (s < 0.0f) ? logf(y / (y + kDENOM()))
                             : logf(kMPN() / (y + kDENOM()));
        acc += (double)t;
    }

    #pragma unroll
    for (int off = 16; off > 0; off >>= 1)
        acc += __shfl_xor_sync(FULL, acc, off);
    __shared__ double sh[8];
    int lane = threadIdx.x & 31, wid = threadIdx.x >> 5;
    if (lane == 0) sh[wid] = acc;
    __syncthreads();
    if (threadIdx.x == 0) {
        double s = 0.0;
        for (int j = 0; j < 8; j++) s += sh[j];
        atomicAdd(&g_loss, s);
    }
}

// --- momentum scatter update of the 256 touched rows
__global__ void k3_update(const float* __restrict__ f_s, const float* __restrict__ f_t,
                          const float* __restrict__ mv1, const float* __restrict__ mv2,
                          const int* __restrict__ idx, float* __restrict__ out) {
    int u = blockIdx.x;       // 512 blocks
    int v = u >> 8;
    int b = u & 255;
    if (!g_winner[b]) return;
    int row = idx[b];
    const float* mem = v ? mv2 : mv1;
    const float* f   = v ? f_t : f_s;
    float* dst = out + 1 + (size_t)v * BANK + (size_t)row * D;
    int t = threadIdx.x;      // 128 threads
    float nv = mem[(long long)row * D + t] * 0.5f + f[b * D + t] * 0.5f;
    float s = nv * nv;
    #pragma unroll
    for (int off = 16; off > 0; off >>= 1)
        s += __shfl_xor_sync(FULL, s, off);
    __shared__ float sh[4];
    if ((t & 31) == 0) sh[t >> 5] = s;
    __syncthreads();
    float tot = sh[0] + sh[1] + sh[2] + sh[3];
    dst[t] = nv / sqrtf(tot);
}

__global__ void k_final(float* __restrict__ out) {
    out[0] = (float)(-g_loss / 256.0);
}

extern "C" void kernel_launch(void* const* d_in, const int* in_sizes, int n_in,
                              void* d_out, int out_size) {
    const float* f_s  = (const float*)d_in[0];
    const float* f_t  = (const float*)d_in[1];
    const float* mv1  = (const float*)d_in[2];
    const float* mv2  = (const float*)d_in[3];
    const int*   idx  = (const int*)d_in[4];
    const int*   cidx = (const int*)d_in[5];
    float* out = (float*)d_out;

    cudaFuncSetAttribute(k_main, cudaFuncAttributeMaxDynamicSharedMemorySize, 66560);

    k_zero<<<32, 256>>>(idx, mv1, mv2, out);
    k_hist<<<1024, 256>>>(idx, cidx);
    k_scan<<<1, 1024>>>();
    k_scatter<<<1024, 256>>>(idx, cidx);
    k_main<<<NBUCK, 256, 65536>>>(f_s, f_t, mv1, mv2, out);
    k2_loss<<<512, 256>>>();
    k3_update<<<512, 128>>>(f_s, f_t, mv1, mv2, idx, out);
    k_final<<<1, 1>>>(out);
}